// round 2
// baseline (speedup 1.0000x reference)
#include <cuda_runtime.h>
#include <math.h>

#define SQ 2048
#define HIDDEN 2048
#define NH 16
#define QLORA 1536
#define KVLORA 512
#define NOPE_D 128
#define ROPE_D 64
#define QHD_D 192
#define VD_D 128
#define KVAW 576            // KVLORA + ROPE
#define HKV 256             // NOPE + VD
#define SOFTMAX_SCALE 0.07216878364870323f   // 192^-0.5

// ------------------- scratch (static device globals; no allocs) -------------
// One big arena + compile-time offsets; kernels reference it directly so the
// host side never needs cudaGetSymbolAddress.
#define OFF_QA     0                                   // 2048*1536
#define OFF_KVA    (OFF_QA    + SQ * QLORA)            // 2048*576
#define OFF_CKV    (OFF_KVA   + SQ * KVAW)             // 2048*512
#define OFF_KPE    (OFF_CKV   + SQ * KVLORA)           // 2048*64
#define OFF_Q      (OFF_KPE   + SQ * ROPE_D)           // 2048*3072
#define OFF_KVEXP  (OFF_Q     + SQ * NH * QHD_D)       // 2048*4096
#define OFF_KHEAD  (OFF_KVEXP + SQ * NH * HKV)         // 16*2048*192
#define OFF_ATTN   (OFF_KHEAD + (size_t)NH * SQ * QHD_D) // 2048*2048
#define OFF_SCORES (OFF_ATTN  + SQ * NH * VD_D)        // 16*2048*2048
#define ARENA_SZ   (OFF_SCORES + (size_t)NH * SQ * SQ)

__device__ float g_arena[ARENA_SZ];

// ------------------- GEMM NT: C = alpha * A(M,K) @ B(N,K)^T -----------------
// Sources/dest selected by arena offsets (negative aoff/boff/coff = use the
// externally supplied pointer instead). blockIdx.z batches via sA/sB/sC.
template <bool CAUSAL>
__global__ void __launch_bounds__(256) sgemm_nt(
    const float* __restrict__ Aext, const float* __restrict__ Bext,
    float* __restrict__ Cext,
    long long aoff, long long boff, long long coff,
    int N, int K, int lda, int ldb, int ldc,
    long long sA, long long sB, long long sC, float alpha)
{
    const float* A = (aoff >= 0 ? g_arena + aoff : Aext) + (size_t)blockIdx.z * sA;
    const float* B = (boff >= 0 ? g_arena + boff : Bext) + (size_t)blockIdx.z * sB;
    float*       C = (coff >= 0 ? g_arena + coff : Cext) + (size_t)blockIdx.z * sC;
    int row0 = blockIdx.y * 128, col0 = blockIdx.x * 128;
    int tid = threadIdx.x;
    int ty = tid >> 4, tx = tid & 15;

    if (CAUSAL && col0 > row0 + 127) {
        // whole tile strictly above the diagonal: write -inf, vectorized
        float4 ninf = make_float4(-INFINITY, -INFINITY, -INFINITY, -INFINITY);
        #pragma unroll
        for (int i = 0; i < 8; i++) {
            float4* rp = (float4*)(C + (size_t)(row0 + ty * 8 + i) * ldc + col0 + tx * 8);
            rp[0] = ninf; rp[1] = ninf;
        }
        return;
    }

    __shared__ float As[8][128];
    __shared__ float Bs[8][128];
    float acc[8][8];
    #pragma unroll
    for (int i = 0; i < 8; i++)
        #pragma unroll
        for (int j = 0; j < 8; j++) acc[i][j] = 0.f;

    int lr = tid >> 1, lc = (tid & 1) * 4;
    bool bvalid = (col0 + lr) < N;
    const float* aptr = A + (size_t)(row0 + lr) * lda + lc;
    const float* bptr = B + (size_t)(col0 + lr) * ldb + lc;

    for (int k0 = 0; k0 < K; k0 += 8) {
        float4 av = *(const float4*)(aptr + k0);
        float4 bv = make_float4(0.f, 0.f, 0.f, 0.f);
        if (bvalid) bv = *(const float4*)(bptr + k0);
        As[lc + 0][lr] = av.x; As[lc + 1][lr] = av.y;
        As[lc + 2][lr] = av.z; As[lc + 3][lr] = av.w;
        Bs[lc + 0][lr] = bv.x; Bs[lc + 1][lr] = bv.y;
        Bs[lc + 2][lr] = bv.z; Bs[lc + 3][lr] = bv.w;
        __syncthreads();
        #pragma unroll
        for (int k = 0; k < 8; k++) {
            float a[8], b[8];
            #pragma unroll
            for (int i = 0; i < 8; i++) a[i] = As[k][ty * 8 + i];
            #pragma unroll
            for (int j = 0; j < 8; j++) b[j] = Bs[k][tx * 8 + j];
            #pragma unroll
            for (int i = 0; i < 8; i++)
                #pragma unroll
                for (int j = 0; j < 8; j++)
                    acc[i][j] = fmaf(a[i], b[j], acc[i][j]);
        }
        __syncthreads();
    }

    #pragma unroll
    for (int i = 0; i < 8; i++) {
        int r = row0 + ty * 8 + i;
        size_t roff = (size_t)r * ldc;
        #pragma unroll
        for (int j = 0; j < 8; j++) {
            int c = col0 + tx * 8 + j;
            if (c < N) {
                float v = acc[i][j] * alpha;
                if (CAUSAL && c > r) v = -INFINITY;
                C[roff + c] = v;
            }
        }
    }
}

// ------------------- GEMM NN: C = A(M,K) @ B(K,N) ---------------------------
// Used only for PV (N=128 exactly). CAUSALK: rows [row0,row0+127] of A have
// nonzeros only at k <= row0+127 -> truncate the K loop.
template <bool CAUSALK>
__global__ void __launch_bounds__(256) sgemm_nn(
    long long aoff, long long boff, long long coff,
    int K, int lda, int ldb, int ldc,
    long long sA, long long sB, long long sC)
{
    const float* A = g_arena + aoff + (size_t)blockIdx.z * sA;
    const float* B = g_arena + boff + (size_t)blockIdx.z * sB;
    float*       C = g_arena + coff + (size_t)blockIdx.z * sC;
    int row0 = blockIdx.y * 128, col0 = blockIdx.x * 128;
    int tid = threadIdx.x;
    int ty = tid >> 4, tx = tid & 15;

    __shared__ float As[8][128];
    __shared__ float Bs[8][128];
    float acc[8][8];
    #pragma unroll
    for (int i = 0; i < 8; i++)
        #pragma unroll
        for (int j = 0; j < 8; j++) acc[i][j] = 0.f;

    int lr = tid >> 1, lc = (tid & 1) * 4;   // A loader
    int br = tid >> 5, bc = (tid & 31) * 4;  // B loader
    int Keff = CAUSALK ? ((row0 + 128 < K) ? row0 + 128 : K) : K;

    for (int k0 = 0; k0 < Keff; k0 += 8) {
        float4 av = *(const float4*)(A + (size_t)(row0 + lr) * lda + k0 + lc);
        float4 bv = *(const float4*)(B + (size_t)(k0 + br) * ldb + col0 + bc);
        As[lc + 0][lr] = av.x; As[lc + 1][lr] = av.y;
        As[lc + 2][lr] = av.z; As[lc + 3][lr] = av.w;
        *(float4*)&Bs[br][bc] = bv;
        __syncthreads();
        #pragma unroll
        for (int k = 0; k < 8; k++) {
            float a[8], b[8];
            #pragma unroll
            for (int i = 0; i < 8; i++) a[i] = As[k][ty * 8 + i];
            #pragma unroll
            for (int j = 0; j < 8; j++) b[j] = Bs[k][tx * 8 + j];
            #pragma unroll
            for (int i = 0; i < 8; i++)
                #pragma unroll
                for (int j = 0; j < 8; j++)
                    acc[i][j] = fmaf(a[i], b[j], acc[i][j]);
        }
        __syncthreads();
    }

    #pragma unroll
    for (int i = 0; i < 8; i++) {
        size_t roff = (size_t)(row0 + ty * 8 + i) * ldc;
        #pragma unroll
        for (int j = 0; j < 8; j++)
            C[roff + col0 + tx * 8 + j] = acc[i][j];
    }
}

// ------------------- RMSNorm on arena rows (in place) -----------------------
__global__ void rmsnorm_kernel(long long xoff, const float* __restrict__ w, int N)
{
    __shared__ float red[32];
    __shared__ float s_inv;
    int row = blockIdx.x, tid = threadIdx.x;
    float* xr = g_arena + xoff + (size_t)row * N;
    float ss = 0.f;
    for (int j = tid; j < N; j += 256) { float v = xr[j]; ss += v * v; }
    for (int o = 16; o; o >>= 1) ss += __shfl_xor_sync(0xffffffffu, ss, o);
    if ((tid & 31) == 0) red[tid >> 5] = ss;
    __syncthreads();
    if (tid < 8) {
        float v = red[tid];
        for (int o = 4; o; o >>= 1) v += __shfl_xor_sync(0xffu, v, o);
        if (tid == 0) s_inv = rsqrtf(v / (float)N + 1e-6f);
    }
    __syncthreads();
    float inv = s_inv;
    for (int j = tid; j < N; j += 256) xr[j] = w[j] * xr[j] * inv;
}

__device__ __forceinline__ float rope_inv_freq(int i)
{
    return (float)pow(10000.0, -(double)(2 * i) / 64.0);
}

// ------------------- kv_a postprocess: rmsnorm(ckv) + RoPE(k_pe) ------------
__global__ void kv_process_kernel(const float* __restrict__ w, const int* __restrict__ pos)
{
    __shared__ float red[32];
    __shared__ float s_inv;
    int row = blockIdx.x, tid = threadIdx.x;
    const float* xr = g_arena + OFF_KVA + (size_t)row * KVAW;
    float* ckv = g_arena + OFF_CKV;
    float* kpe = g_arena + OFF_KPE;
    float ss = 0.f;
    for (int j = tid; j < KVLORA; j += 256) { float v = xr[j]; ss += v * v; }
    for (int o = 16; o; o >>= 1) ss += __shfl_xor_sync(0xffffffffu, ss, o);
    if ((tid & 31) == 0) red[tid >> 5] = ss;
    __syncthreads();
    if (tid < 8) {
        float v = red[tid];
        for (int o = 4; o; o >>= 1) v += __shfl_xor_sync(0xffu, v, o);
        if (tid == 0) s_inv = rsqrtf(v / (float)KVLORA + 1e-6f);
    }
    __syncthreads();
    float inv = s_inv;
    for (int j = tid; j < KVLORA; j += 256)
        ckv[(size_t)row * KVLORA + j] = w[j] * xr[j] * inv;
    if (tid < 32) {
        int i = tid;
        float xlo = xr[KVLORA + i], xhi = xr[KVLORA + 32 + i];
        float ang = (float)pos[row] * rope_inv_freq(i);
        float c = cosf(ang), s = sinf(ang);
        kpe[(size_t)row * ROPE_D + i]      = xlo * c - xhi * s;
        kpe[(size_t)row * ROPE_D + 32 + i] = xhi * c + xlo * s;
    }
}

// ------------------- RoPE on q_pe (in place) --------------------------------
__global__ void rope_q_kernel(const int* __restrict__ pos)
{
    int idx = blockIdx.x * 256 + threadIdx.x;
    if (idx >= SQ * NH * 32) return;
    int i = idx & 31;
    int h = (idx >> 5) & (NH - 1);
    int s = idx >> 9;
    float* b = g_arena + OFF_Q + (size_t)s * (NH * QHD_D) + h * QHD_D + NOPE_D;
    float xlo = b[i], xhi = b[32 + i];
    float ang = (float)pos[s] * rope_inv_freq(i);
    float c = cosf(ang), sn = sinf(ang);
    b[i]      = xlo * c - xhi * sn;
    b[32 + i] = xhi * c + xlo * sn;
}

// ------------------- pack K heads: [h][t][0:128]=k_nope, [128:192]=k_pe -----
__global__ void pack_k_kernel()
{
    size_t idx = (size_t)blockIdx.x * 256 + threadIdx.x;
    if (idx >= (size_t)NH * SQ * QHD_D) return;
    int d = (int)(idx % QHD_D);
    int t = (int)((idx / QHD_D) % SQ);
    int h = (int)(idx / ((size_t)QHD_D * SQ));
    float v = (d < NOPE_D) ? g_arena[OFF_KVEXP + (size_t)t * (NH * HKV) + h * HKV + d]
                           : g_arena[OFF_KPE + (size_t)t * ROPE_D + (d - NOPE_D)];
    g_arena[OFF_KHEAD + idx] = v;
}

// ------------------- row softmax over S=2048 (one block per (h,s)) ----------
__global__ void softmax_kernel()
{
    __shared__ float red[32];
    int row = blockIdx.x;
    float* r = g_arena + OFF_SCORES + (size_t)row * SQ;
    int tid = threadIdx.x;
    float ev[8];
    float m = -INFINITY;
    #pragma unroll
    for (int it = 0; it < 8; ++it) { ev[it] = r[tid + it * 256]; m = fmaxf(m, ev[it]); }
    for (int o = 16; o; o >>= 1) m = fmaxf(m, __shfl_xor_sync(0xffffffffu, m, o));
    if ((tid & 31) == 0) red[tid >> 5] = m;
    __syncthreads();
    if (tid < 8) {
        float v = red[tid];
        for (int o = 4; o; o >>= 1) v = fmaxf(v, __shfl_xor_sync(0xffu, v, o));
        if (tid == 0) red[0] = v;
    }
    __syncthreads();
    m = red[0];
    __syncthreads();
    float sum = 0.f;
    #pragma unroll
    for (int it = 0; it < 8; ++it) { ev[it] = expf(ev[it] - m); sum += ev[it]; }
    for (int o = 16; o; o >>= 1) sum += __shfl_xor_sync(0xffffffffu, sum, o);
    if ((tid & 31) == 0) red[tid >> 5] = sum;
    __syncthreads();
    if (tid < 8) {
        float v = red[tid];
        for (int o = 4; o; o >>= 1) v += __shfl_xor_sync(0xffu, v, o);
        if (tid == 0) red[0] = v;
    }
    __syncthreads();
    float inv = 1.f / red[0];
    #pragma unroll
    for (int it = 0; it < 8; ++it) r[tid + it * 256] = ev[it] * inv;
}

// ---------------------------------------------------------------------------
extern "C" void kernel_launch(void* const* d_in, const int* in_sizes, int n_in,
                              void* d_out, int out_size)
{
    const float* hidden  = (const float*)d_in[0];
    const int*   pos     = (const int*)d_in[1];
    const float* q_a_w   = (const float*)d_in[2];
    const float* q_a_ln  = (const float*)d_in[3];
    const float* q_b_w   = (const float*)d_in[4];
    const float* kv_a_w  = (const float*)d_in[5];
    const float* kv_a_ln = (const float*)d_in[6];
    const float* kv_b_w  = (const float*)d_in[7];
    const float* o_w     = (const float*)d_in[8];
    float* out = (float*)d_out;

    // 1) q_a = hidden @ q_a_w^T               [2048, 1536]
    sgemm_nt<false><<<dim3(QLORA / 128, SQ / 128, 1), 256>>>(
        hidden, q_a_w, nullptr, -1, -1, OFF_QA,
        QLORA, HIDDEN, HIDDEN, HIDDEN, QLORA, 0, 0, 0, 1.f);
    // 2) kv = hidden @ kv_a_w^T               [2048, 576]
    sgemm_nt<false><<<dim3((KVAW + 127) / 128, SQ / 128, 1), 256>>>(
        hidden, kv_a_w, nullptr, -1, -1, OFF_KVA,
        KVAW, HIDDEN, HIDDEN, HIDDEN, KVAW, 0, 0, 0, 1.f);
    // 3) rmsnorm(q_a) in place
    rmsnorm_kernel<<<SQ, 256>>>(OFF_QA, q_a_ln, QLORA);
    // 4) rmsnorm(ckv) + RoPE(k_pe)
    kv_process_kernel<<<SQ, 256>>>(kv_a_ln, pos);
    // 5) q = qa_n @ q_b_w^T                   [2048, 3072]
    sgemm_nt<false><<<dim3(NH * QHD_D / 128, SQ / 128, 1), 256>>>(
        nullptr, q_b_w, nullptr, OFF_QA, -1, OFF_Q,
        NH * QHD_D, QLORA, QLORA, QLORA, NH * QHD_D, 0, 0, 0, 1.f);
    // 6) RoPE on q_pe in place
    rope_q_kernel<<<(SQ * NH * 32 + 255) / 256, 256>>>(pos);
    // 7) kv_exp = ckv @ kv_b_w^T              [2048, 4096]
    sgemm_nt<false><<<dim3(NH * HKV / 128, SQ / 128, 1), 256>>>(
        nullptr, kv_b_w, nullptr, OFF_CKV, -1, OFF_KVEXP,
        NH * HKV, KVLORA, KVLORA, KVLORA, NH * HKV, 0, 0, 0, 1.f);
    // 8) pack K per head
    pack_k_kernel<<<(int)(((size_t)NH * SQ * QHD_D + 255) / 256), 256>>>();
    // 9) scores[h] = scale * Q_h @ K_h^T, causal mask    [16][2048][2048]
    sgemm_nt<true><<<dim3(SQ / 128, SQ / 128, NH), 256>>>(
        nullptr, nullptr, nullptr, OFF_Q, OFF_KHEAD, OFF_SCORES,
        SQ, QHD_D, NH * QHD_D, QHD_D, SQ,
        (long long)QHD_D, (long long)SQ * QHD_D, (long long)SQ * SQ, SOFTMAX_SCALE);
    // 10) softmax rows
    softmax_kernel<<<NH * SQ, 256>>>();
    // 11) attn[h] = P_h @ V_h   (K-loop truncated by causality)
    sgemm_nn<true><<<dim3(VD_D / 128, SQ / 128, NH), 256>>>(
        OFF_SCORES, OFF_KVEXP + NOPE_D, OFF_ATTN,
        SQ, SQ, NH * HKV, NH * VD_D,
        (long long)SQ * SQ, (long long)HKV, (long long)VD_D);
    // 12) out = attn @ o_w^T                  [2048, 2048]
    sgemm_nt<false><<<dim3(HIDDEN / 128, SQ / 128, 1), 256>>>(
        nullptr, o_w, out, OFF_ATTN, -1, -1,
        HIDDEN, HIDDEN, HIDDEN, HIDDEN, HIDDEN, 0, 0, 0, 1.f);
}

// round 4
// speedup vs baseline: 2.3876x; 2.3876x over previous
#include <cuda_runtime.h>
#include <math.h>

#define SQ 2048
#define HIDDEN 2048
#define NH 16
#define QLORA 1536
#define KVLORA 512
#define NOPE_D 128
#define ROPE_D 64
#define QHD_D 192
#define VD_D 128
#define KVAW 576            // KVLORA + ROPE
#define HKV 256             // NOPE + VD
#define SOFTMAX_SCALE 0.07216878364870323f   // 192^-0.5

#define BK 32
#define SPAD 136            // SMEM row stride (words); (136%32)=8 -> conflict-free frags

// ------------------- scratch arena (static device global) -------------------
#define OFF_QA     0
#define OFF_KVA    (OFF_QA    + SQ * QLORA)
#define OFF_CKV    (OFF_KVA   + SQ * KVAW)
#define OFF_KPE    (OFF_CKV   + SQ * KVLORA)
#define OFF_Q      (OFF_KPE   + SQ * ROPE_D)
#define OFF_KVEXP  (OFF_Q     + SQ * NH * QHD_D)
#define OFF_KHEAD  (OFF_KVEXP + SQ * NH * HKV)
#define OFF_ATTN   (OFF_KHEAD + (size_t)NH * SQ * QHD_D)
#define OFF_SCORES (OFF_ATTN  + SQ * NH * VD_D)
#define ARENA_SZ   (OFF_SCORES + (size_t)NH * SQ * SQ)

__device__ float g_arena[ARENA_SZ];

// ------------------- tf32 helpers -------------------------------------------
__device__ __forceinline__ unsigned f2tf(float f)
{
    unsigned u;
    asm("cvt.rna.tf32.f32 %0, %1;" : "=r"(u) : "f"(f));
    return u;
}

__device__ __forceinline__ void mma_tf32(float c[4], const unsigned a[4], const unsigned b[2])
{
    asm volatile(
        "mma.sync.aligned.m16n8k8.row.col.f32.tf32.tf32.f32 "
        "{%0,%1,%2,%3}, {%4,%5,%6,%7}, {%8,%9}, {%0,%1,%2,%3};\n"
        : "+f"(c[0]), "+f"(c[1]), "+f"(c[2]), "+f"(c[3])
        : "r"(a[0]), "r"(a[1]), "r"(a[2]), "r"(a[3]), "r"(b[0]), "r"(b[1]));
}

// Shared compute core: one BK=32 chunk. As/Bs are [BK][SPAD], k-major.
// Warp layout: 8 warps as 2x4; each warp owns 64x32 of the 128x128 C tile.
__device__ __forceinline__ void mma_chunk(
    const unsigned (*As)[SPAD], const unsigned (*Bs)[SPAD],
    int mb, int nb, int grp, int tig, float c[4][4][4])
{
    #pragma unroll
    for (int k8 = 0; k8 < 4; k8++) {
        int kb = k8 * 8;
        unsigned af[4][4], bf[4][2];
        #pragma unroll
        for (int mt = 0; mt < 4; mt++) {
            int m = mb + mt * 16 + grp;
            af[mt][0] = As[kb + tig][m];
            af[mt][1] = As[kb + tig][m + 8];
            af[mt][2] = As[kb + tig + 4][m];
            af[mt][3] = As[kb + tig + 4][m + 8];
        }
        #pragma unroll
        for (int nt = 0; nt < 4; nt++) {
            int n = nb + nt * 8 + grp;
            bf[nt][0] = Bs[kb + tig][n];
            bf[nt][1] = Bs[kb + tig + 4][n];
        }
        #pragma unroll
        for (int mt = 0; mt < 4; mt++)
            #pragma unroll
            for (int nt = 0; nt < 4; nt++)
                mma_tf32(c[mt][nt], af[mt], bf[nt]);
    }
}

// ------------------- GEMM NT: C = alpha * A(M,K) @ B(N,K)^T -----------------
template <bool CAUSAL>
__global__ void __launch_bounds__(256) tgemm_nt(
    const float* __restrict__ Aext, const float* __restrict__ Bext,
    float* __restrict__ Cext,
    long long aoff, long long boff, long long coff,
    int N, int K, int lda, int ldb, int ldc,
    long long sA, long long sB, long long sC, float alpha)
{
    const float* A = (aoff >= 0 ? g_arena + aoff : Aext) + (size_t)blockIdx.z * sA;
    const float* B = (boff >= 0 ? g_arena + boff : Bext) + (size_t)blockIdx.z * sB;
    float*       C = (coff >= 0 ? g_arena + coff : Cext) + (size_t)blockIdx.z * sC;
    int row0 = blockIdx.y * 128, col0 = blockIdx.x * 128;
    int tid = threadIdx.x;

    if (CAUSAL && col0 > row0 + 127) {
        int ty = tid >> 4, tx = tid & 15;
        float4 ninf = make_float4(-INFINITY, -INFINITY, -INFINITY, -INFINITY);
        #pragma unroll
        for (int i = 0; i < 8; i++) {
            float4* rp = (float4*)(C + (size_t)(row0 + ty * 8 + i) * ldc + col0 + tx * 8);
            rp[0] = ninf; rp[1] = ninf;
        }
        return;
    }

    __shared__ unsigned As[BK][SPAD];
    __shared__ unsigned Bs[BK][SPAD];

    int wid = tid >> 5, lane = tid & 31;
    int mb = (wid >> 2) * 64, nb = (wid & 3) * 32;
    int grp = lane >> 2, tig = lane & 3;

    float c[4][4][4];
    #pragma unroll
    for (int mt = 0; mt < 4; mt++)
        #pragma unroll
        for (int nt = 0; nt < 4; nt++)
            #pragma unroll
            for (int e = 0; e < 4; e++) c[mt][nt][e] = 0.f;

    int lr = tid >> 1, lc = (tid & 1) * 16;
    bool bvalid = (col0 + lr) < N;
    const float* aptr = A + (size_t)(row0 + lr) * lda + lc;
    const float* bptr = B + (size_t)(col0 + lr) * ldb + lc;

    for (int k0 = 0; k0 < K; k0 += BK) {
        #pragma unroll
        for (int j = 0; j < 4; j++) {
            float4 v = *(const float4*)(aptr + k0 + j * 4);
            int kk = lc + j * 4;
            As[kk + 0][lr] = f2tf(v.x); As[kk + 1][lr] = f2tf(v.y);
            As[kk + 2][lr] = f2tf(v.z); As[kk + 3][lr] = f2tf(v.w);
            float4 w = make_float4(0.f, 0.f, 0.f, 0.f);
            if (bvalid) w = *(const float4*)(bptr + k0 + j * 4);
            Bs[kk + 0][lr] = f2tf(w.x); Bs[kk + 1][lr] = f2tf(w.y);
            Bs[kk + 2][lr] = f2tf(w.z); Bs[kk + 3][lr] = f2tf(w.w);
        }
        __syncthreads();
        mma_chunk(As, Bs, mb, nb, grp, tig, c);
        __syncthreads();
    }

    #pragma unroll
    for (int mt = 0; mt < 4; mt++) {
        int r0 = row0 + mb + mt * 16 + grp;
        #pragma unroll
        for (int nt = 0; nt < 4; nt++) {
            int cg = col0 + nb + nt * 8 + tig * 2;
            #pragma unroll
            for (int e = 0; e < 4; e++) {
                int r = r0 + (e >> 1) * 8;
                int cc = cg + (e & 1);
                if (cc < N) {
                    float v = c[mt][nt][e] * alpha;
                    if (CAUSAL && cc > r) v = -INFINITY;
                    C[(size_t)r * ldc + cc] = v;
                }
            }
        }
    }
}

// ------------------- GEMM NN: C = A(M,K) @ B(K,N), N multiple of 128 --------
template <bool CAUSALK>
__global__ void __launch_bounds__(256) tgemm_nn(
    long long aoff, long long boff, long long coff,
    int K, int lda, int ldb, int ldc,
    long long sA, long long sB, long long sC)
{
    const float* A = g_arena + aoff + (size_t)blockIdx.z * sA;
    const float* B = g_arena + boff + (size_t)blockIdx.z * sB;
    float*       C = g_arena + coff + (size_t)blockIdx.z * sC;
    int row0 = blockIdx.y * 128, col0 = blockIdx.x * 128;
    int tid = threadIdx.x;

    __shared__ unsigned As[BK][SPAD];
    __shared__ unsigned Bs[BK][SPAD];

    int wid = tid >> 5, lane = tid & 31;
    int mb = (wid >> 2) * 64, nb = (wid & 3) * 32;
    int grp = lane >> 2, tig = lane & 3;

    float c[4][4][4];
    #pragma unroll
    for (int mt = 0; mt < 4; mt++)
        #pragma unroll
        for (int nt = 0; nt < 4; nt++)
            #pragma unroll
            for (int e = 0; e < 4; e++) c[mt][nt][e] = 0.f;

    int lr = tid >> 1, lc = (tid & 1) * 16;   // A loader
    int br = tid >> 3, bc = (tid & 7) * 16;   // B loader (k=br, n=bc..)
    const float* aptr = A + (size_t)(row0 + lr) * lda + lc;
    int Keff = CAUSALK ? ((row0 + 128 < K) ? row0 + 128 : K) : K;

    for (int k0 = 0; k0 < Keff; k0 += BK) {
        #pragma unroll
        for (int j = 0; j < 4; j++) {
            float4 v = *(const float4*)(aptr + k0 + j * 4);
            int kk = lc + j * 4;
            As[kk + 0][lr] = f2tf(v.x); As[kk + 1][lr] = f2tf(v.y);
            As[kk + 2][lr] = f2tf(v.z); As[kk + 3][lr] = f2tf(v.w);
        }
        const float* bptr = B + (size_t)(k0 + br) * ldb + col0 + bc;
        #pragma unroll
        for (int j = 0; j < 4; j++) {
            float4 w = *(const float4*)(bptr + j * 4);
            int nn = bc + j * 4;
            Bs[br][nn + 0] = f2tf(w.x); Bs[br][nn + 1] = f2tf(w.y);
            Bs[br][nn + 2] = f2tf(w.z); Bs[br][nn + 3] = f2tf(w.w);
        }
        __syncthreads();
        mma_chunk(As, Bs, mb, nb, grp, tig, c);
        __syncthreads();
    }

    #pragma unroll
    for (int mt = 0; mt < 4; mt++) {
        int r0 = row0 + mb + mt * 16 + grp;
        #pragma unroll
        for (int nt = 0; nt < 4; nt++) {
            int cg = col0 + nb + nt * 8 + tig * 2;
            C[(size_t)r0 * ldc + cg]           = c[mt][nt][0];
            C[(size_t)r0 * ldc + cg + 1]       = c[mt][nt][1];
            C[(size_t)(r0 + 8) * ldc + cg]     = c[mt][nt][2];
            C[(size_t)(r0 + 8) * ldc + cg + 1] = c[mt][nt][3];
        }
    }
}

// ------------------- RMSNorm on arena rows (in place) -----------------------
__global__ void rmsnorm_kernel(long long xoff, const float* __restrict__ w, int N)
{
    __shared__ float red[32];
    __shared__ float s_inv;
    int row = blockIdx.x, tid = threadIdx.x;
    float* xr = g_arena + xoff + (size_t)row * N;
    float ss = 0.f;
    for (int j = tid; j < N; j += 256) { float v = xr[j]; ss += v * v; }
    for (int o = 16; o; o >>= 1) ss += __shfl_xor_sync(0xffffffffu, ss, o);
    if ((tid & 31) == 0) red[tid >> 5] = ss;
    __syncthreads();
    if (tid < 8) {
        float v = red[tid];
        for (int o = 4; o; o >>= 1) v += __shfl_xor_sync(0xffu, v, o);
        if (tid == 0) s_inv = rsqrtf(v / (float)N + 1e-6f);
    }
    __syncthreads();
    float inv = s_inv;
    for (int j = tid; j < N; j += 256) xr[j] = w[j] * xr[j] * inv;
}

__device__ __forceinline__ float rope_inv_freq(int i)
{
    return (float)pow(10000.0, -(double)(2 * i) / 64.0);
}

// ------------------- kv_a postprocess: rmsnorm(ckv) + RoPE(k_pe) ------------
__global__ void kv_process_kernel(const float* __restrict__ w, const int* __restrict__ pos)
{
    __shared__ float red[32];
    __shared__ float s_inv;
    int row = blockIdx.x, tid = threadIdx.x;
    const float* xr = g_arena + OFF_KVA + (size_t)row * KVAW;
    float* ckv = g_arena + OFF_CKV;
    float* kpe = g_arena + OFF_KPE;
    float ss = 0.f;
    for (int j = tid; j < KVLORA; j += 256) { float v = xr[j]; ss += v * v; }
    for (int o = 16; o; o >>= 1) ss += __shfl_xor_sync(0xffffffffu, ss, o);
    if ((tid & 31) == 0) red[tid >> 5] = ss;
    __syncthreads();
    if (tid < 8) {
        float v = red[tid];
        for (int o = 4; o; o >>= 1) v += __shfl_xor_sync(0xffu, v, o);
        if (tid == 0) s_inv = rsqrtf(v / (float)KVLORA + 1e-6f);
    }
    __syncthreads();
    float inv = s_inv;
    for (int j = tid; j < KVLORA; j += 256)
        ckv[(size_t)row * KVLORA + j] = w[j] * xr[j] * inv;
    if (tid < 32) {
        int i = tid;
        float xlo = xr[KVLORA + i], xhi = xr[KVLORA + 32 + i];
        float ang = (float)pos[row] * rope_inv_freq(i);
        float c = cosf(ang), s = sinf(ang);
        kpe[(size_t)row * ROPE_D + i]      = xlo * c - xhi * s;
        kpe[(size_t)row * ROPE_D + 32 + i] = xhi * c + xlo * s;
    }
}

// ------------------- RoPE on q_pe (in place) --------------------------------
__global__ void rope_q_kernel(const int* __restrict__ pos)
{
    int idx = blockIdx.x * 256 + threadIdx.x;
    if (idx >= SQ * NH * 32) return;
    int i = idx & 31;
    int h = (idx >> 5) & (NH - 1);
    int s = idx >> 9;
    float* b = g_arena + OFF_Q + (size_t)s * (NH * QHD_D) + h * QHD_D + NOPE_D;
    float xlo = b[i], xhi = b[32 + i];
    float ang = (float)pos[s] * rope_inv_freq(i);
    float c = cosf(ang), sn = sinf(ang);
    b[i]      = xlo * c - xhi * sn;
    b[32 + i] = xhi * c + xlo * sn;
}

// ------------------- pack K heads: [h][t][0:128]=k_nope, [128:192]=k_pe -----
__global__ void pack_k_kernel()
{
    size_t idx = (size_t)blockIdx.x * 256 + threadIdx.x;
    if (idx >= (size_t)NH * SQ * QHD_D) return;
    int d = (int)(idx % QHD_D);
    int t = (int)((idx / QHD_D) % SQ);
    int h = (int)(idx / ((size_t)QHD_D * SQ));
    float v = (d < NOPE_D) ? g_arena[OFF_KVEXP + (size_t)t * (NH * HKV) + h * HKV + d]
                           : g_arena[OFF_KPE + (size_t)t * ROPE_D + (d - NOPE_D)];
    g_arena[OFF_KHEAD + idx] = v;
}

// ------------------- row softmax over S=2048 (one block per (h,s)) ----------
__global__ void softmax_kernel()
{
    __shared__ float red[32];
    int row = blockIdx.x;
    float* r = g_arena + OFF_SCORES + (size_t)row * SQ;
    int tid = threadIdx.x;
    float ev[8];
    float m = -INFINITY;
    #pragma unroll
    for (int it = 0; it < 8; ++it) { ev[it] = r[tid + it * 256]; m = fmaxf(m, ev[it]); }
    for (int o = 16; o; o >>= 1) m = fmaxf(m, __shfl_xor_sync(0xffffffffu, m, o));
    if ((tid & 31) == 0) red[tid >> 5] = m;
    __syncthreads();
    if (tid < 8) {
        float v = red[tid];
        for (int o = 4; o; o >>= 1) v = fmaxf(v, __shfl_xor_sync(0xffu, v, o));
        if (tid == 0) red[0] = v;
    }
    __syncthreads();
    m = red[0];
    __syncthreads();
    float sum = 0.f;
    #pragma unroll
    for (int it = 0; it < 8; ++it) { ev[it] = expf(ev[it] - m); sum += ev[it]; }
    for (int o = 16; o; o >>= 1) sum += __shfl_xor_sync(0xffffffffu, sum, o);
    if ((tid & 31) == 0) red[tid >> 5] = sum;
    __syncthreads();
    if (tid < 8) {
        float v = red[tid];
        for (int o = 4; o; o >>= 1) v += __shfl_xor_sync(0xffu, v, o);
        if (tid == 0) red[0] = v;
    }
    __syncthreads();
    float inv = 1.f / red[0];
    #pragma unroll
    for (int it = 0; it < 8; ++it) r[tid + it * 256] = ev[it] * inv;
}

// ---------------------------------------------------------------------------
extern "C" void kernel_launch(void* const* d_in, const int* in_sizes, int n_in,
                              void* d_out, int out_size)
{
    const float* hidden  = (const float*)d_in[0];
    const int*   pos     = (const int*)d_in[1];
    const float* q_a_w   = (const float*)d_in[2];
    const float* q_a_ln  = (const float*)d_in[3];
    const float* q_b_w   = (const float*)d_in[4];
    const float* kv_a_w  = (const float*)d_in[5];
    const float* kv_a_ln = (const float*)d_in[6];
    const float* kv_b_w  = (const float*)d_in[7];
    const float* o_w     = (const float*)d_in[8];
    float* out = (float*)d_out;

    // 1) q_a = hidden @ q_a_w^T               [2048, 1536]
    tgemm_nt<false><<<dim3(QLORA / 128, SQ / 128, 1), 256>>>(
        hidden, q_a_w, nullptr, -1, -1, OFF_QA,
        QLORA, HIDDEN, HIDDEN, HIDDEN, QLORA, 0, 0, 0, 1.f);
    // 2) kv = hidden @ kv_a_w^T               [2048, 576]
    tgemm_nt<false><<<dim3((KVAW + 127) / 128, SQ / 128, 1), 256>>>(
        hidden, kv_a_w, nullptr, -1, -1, OFF_KVA,
        KVAW, HIDDEN, HIDDEN, HIDDEN, KVAW, 0, 0, 0, 1.f);
    // 3) rmsnorm(q_a) in place
    rmsnorm_kernel<<<SQ, 256>>>(OFF_QA, q_a_ln, QLORA);
    // 4) rmsnorm(ckv) + RoPE(k_pe)
    kv_process_kernel<<<SQ, 256>>>(kv_a_ln, pos);
    // 5) q = qa_n @ q_b_w^T                   [2048, 3072]
    tgemm_nt<false><<<dim3(NH * QHD_D / 128, SQ / 128, 1), 256>>>(
        nullptr, q_b_w, nullptr, OFF_QA, -1, OFF_Q,
        NH * QHD_D, QLORA, QLORA, QLORA, NH * QHD_D, 0, 0, 0, 1.f);
    // 6) RoPE on q_pe in place
    rope_q_kernel<<<(SQ * NH * 32 + 255) / 256, 256>>>(pos);
    // 7) kv_exp = ckv @ kv_b_w^T              [2048, 4096]
    tgemm_nt<false><<<dim3(NH * HKV / 128, SQ / 128, 1), 256>>>(
        nullptr, kv_b_w, nullptr, OFF_CKV, -1, OFF_KVEXP,
        NH * HKV, KVLORA, KVLORA, KVLORA, NH * HKV, 0, 0, 0, 1.f);
    // 8) pack K per head
    pack_k_kernel<<<(int)(((size_t)NH * SQ * QHD_D + 255) / 256), 256>>>();
    // 9) scores[h] = scale * Q_h @ K_h^T, causal mask    [16][2048][2048]
    tgemm_nt<true><<<dim3(SQ / 128, SQ / 128, NH), 256>>>(
        nullptr, nullptr, nullptr, OFF_Q, OFF_KHEAD, OFF_SCORES,
        SQ, QHD_D, NH * QHD_D, QHD_D, SQ,
        (long long)QHD_D, (long long)SQ * QHD_D, (long long)SQ * SQ, SOFTMAX_SCALE);
    // 10) softmax rows
    softmax_kernel<<<NH * SQ, 256>>>();
    // 11) attn[h] = P_h @ V_h   (K-loop truncated by causality)
    tgemm_nn<true><<<dim3(VD_D / 128, SQ / 128, NH), 256>>>(
        OFF_SCORES, OFF_KVEXP + NOPE_D, OFF_ATTN,
        SQ, SQ, NH * HKV, NH * VD_D,
        (long long)SQ * SQ, (long long)HKV, (long long)VD_D);
    // 12) out = attn @ o_w^T                  [2048, 2048]
    tgemm_nt<false><<<dim3(HIDDEN / 128, SQ / 128, 1), 256>>>(
        nullptr, o_w, out, OFF_ATTN, -1, -1,
        HIDDEN, HIDDEN, HIDDEN, HIDDEN, HIDDEN, 0, 0, 0, 1.f);
}